// round 6
// baseline (speedup 1.0000x reference)
#include <cuda_runtime.h>

// PPO loss + GAE, B=4096 x T=2048.
//
// 3 launches (graph-capturable, allocation-free):
//   1. gae:  one warp per row. Blocked affine suffix scan, CHUNK=16 steps
//            per lane -> 512 timesteps per warp scan, 4 segments per row.
//            `values` is loaded with coalesced stride-32 lane pattern and
//            transposed through padded shared memory (conflict-free reads),
//            fixing the 8x L1 wavefront amplification of scalar loads.
//            Accumulates sum(adv), sum(adv^2); value_loss = mean(adv^2).
//   2. loss: mean/rstd from the accumulators, grid-stride paired-float4
//            pass for the clipped PPO surrogate + entropy.
//   3. finalize: writes the 4 scalars and resets accumulators for replay.

namespace {
constexpr int B = 4096;
constexpr int T = 2048;
constexpr long long NTOT = (long long)B * T;   // 8388608
constexpr float GAMMA = 0.99f;
constexpr float LAM   = 0.95f;
constexpr float GL    = GAMMA * LAM;
constexpr float CLIPP = 0.2f;
constexpr float EPSF  = 1e-9f;
constexpr int CHUNK = 16;                // timesteps per lane per segment
constexpr int SEG   = 32 * CHUNK;        // 512 timesteps per warp scan
constexpr int NSEG  = T / SEG;           // 4
constexpr int VPAD  = 560;               // >= pad(512)+1 = 545, padded
}

__device__ float  g_adv[(size_t)B * T];  // 32 MB unnormalized advantages
__device__ double g_sum, g_sumsq, g_ppo, g_ent;   // zero-initialized

__device__ __forceinline__ int vpad(int p) { return p + (p >> 4); }

// ---------------------------------------------------------------- pass 1
__global__ __launch_bounds__(128, 6) void gae_kernel(
    const float* __restrict__ rewards,
    const float* __restrict__ values,
    const float* __restrict__ masks)
{
    __shared__ float s_v[4][VPAD];

    const int gwarp = (blockIdx.x * blockDim.x + threadIdx.x) >> 5;  // row
    const int lane  = threadIdx.x & 31;
    const int wid   = threadIdx.x >> 5;
    const unsigned FULL = 0xffffffffu;

    float lsum = 0.f, lsq = 0.f;

    if (gwarp < B) {
        const float* rr = rewards + (size_t)gwarp * T;
        const float* vr = values  + (size_t)gwarp * (T + 1);
        const float* mr = masks   + (size_t)gwarp * T;
        float*       ar = g_adv   + (size_t)gwarp * T;

        float carry = 0.f;   // adv just past the current segment (adv[T]=0)

        for (int seg = NSEG - 1; seg >= 0; --seg) {
            const int sb   = seg * SEG;          // segment start (timestep)
            const int base = sb + lane * CHUNK;  // this lane's chunk start

            // ---- values: coalesced stride-32 loads -> padded smem ----
            #pragma unroll
            for (int k = 0; k < CHUNK; ++k) {
                const int p = k * 32 + lane;
                s_v[wid][vpad(p)] = __ldcs(vr + sb + p);
            }
            if (lane == 0) s_v[wid][vpad(SEG)] = __ldcs(vr + sb + SEG);
            __syncwarp();

            // ---- rewards/masks: float4 coalesced ----
            float4 rv[CHUNK / 4], mv[CHUNK / 4];
            #pragma unroll
            for (int q = 0; q < CHUNK / 4; ++q) {
                rv[q] = __ldcs((const float4*)(rr + base) + q);
                mv[q] = __ldcs((const float4*)(mr + base) + q);
            }
            const float* r_ = (const float*)rv;
            const float* m_ = (const float*)mv;

            // ---- per-step affine coefficients ----
            // adv[t] = d[t] + c[t]*adv[t+1]
            float c[CHUNK], d[CHUNK];
            {
                const int rb = lane * CHUNK;     // row offset into smem tile
                float vj = s_v[wid][vpad(rb)];   // v at base
                #pragma unroll
                for (int j = 0; j < CHUNK; ++j) {
                    const float vn = s_v[wid][vpad(rb + j + 1)];
                    c[j] = GL * m_[j];
                    d[j] = fmaf(GAMMA * vn, m_[j], r_[j]) - vj;
                    vj = vn;
                }
            }
            __syncwarp();   // reads done before next segment's stores

            // ---- local suffix composition over this lane's 16 steps ----
            float C = c[CHUNK - 1], D = d[CHUNK - 1];
            #pragma unroll
            for (int j = CHUNK - 2; j >= 0; --j) {
                D = fmaf(c[j], D, d[j]);
                C = c[j] * C;
            }

            // ---- warp inclusive suffix scan of the 32 per-lane maps ----
            #pragma unroll
            for (int off = 1; off < 32; off <<= 1) {
                const float C2 = __shfl_down_sync(FULL, C, off);
                const float D2 = __shfl_down_sync(FULL, D, off);
                if (lane + off < 32) {
                    D = fmaf(C, D2, D);
                    C = C * C2;
                }
            }

            // x = adv at my chunk's end+1 (maps of lanes > me applied to carry)
            const float Cx = __shfl_down_sync(FULL, C, 1);
            const float Dx = __shfl_down_sync(FULL, D, 1);
            float x = (lane == 31) ? carry : fmaf(Cx, carry, Dx);

            // ---- unroll my 16 advantages (reverse time) ----
            float a[CHUNK];
            #pragma unroll
            for (int j = CHUNK - 1; j >= 0; --j) {
                a[j] = fmaf(c[j], x, d[j]);
                x = a[j];
            }
            carry = __shfl_sync(FULL, x, 0);     // adv[sb] for the next segment

            #pragma unroll
            for (int q = 0; q < CHUNK / 4; ++q) {
                ((float4*)(ar + base))[q] =
                    make_float4(a[4*q], a[4*q+1], a[4*q+2], a[4*q+3]);
            }

            #pragma unroll
            for (int j = 0; j < CHUNK; ++j) {
                lsum += a[j];
                lsq = fmaf(a[j], a[j], lsq);
            }
        }
    }

    #pragma unroll
    for (int off = 16; off; off >>= 1) {
        lsum += __shfl_down_sync(FULL, lsum, off);
        lsq  += __shfl_down_sync(FULL, lsq,  off);
    }

    __shared__ double s_sum[4], s_sq[4];
    if (lane == 0) { s_sum[wid] = (double)lsum; s_sq[wid] = (double)lsq; }
    __syncthreads();
    if (threadIdx.x == 0) {
        double bs = 0.0, bq = 0.0;
        #pragma unroll
        for (int i = 0; i < 4; ++i) { bs += s_sum[i]; bq += s_sq[i]; }
        atomicAdd(&g_sum,   bs);
        atomicAdd(&g_sumsq, bq);
    }
}

// ---------------------------------------------------------------- pass 2
__global__ __launch_bounds__(256) void loss_kernel(
    const float* __restrict__ old_p,
    const float* __restrict__ curr_p)
{
    __shared__ float sh_mean, sh_rstd;
    if (threadIdx.x == 0) {
        const double n    = (double)NTOT;
        const double mean = g_sum / n;
        const double var  = (g_sumsq - g_sum * g_sum / n) / (n - 1.0);  // ddof=1
        sh_mean = (float)mean;
        sh_rstd = (float)(1.0 / (sqrt(var) + (double)EPSF));
    }
    __syncthreads();
    const float mean = sh_mean, rstd = sh_rstd;

    const int n4 = (int)(NTOT / 4);
    const float4* a4 = (const float4*)g_adv;
    const float4* o4 = (const float4*)old_p;
    const float4* c4 = (const float4*)curr_p;

    float ppo = 0.f, ent = 0.f;
    const int stride = gridDim.x * blockDim.x;

    for (int i = blockIdx.x * blockDim.x + threadIdx.x; i < n4; i += 2 * stride) {
        const int j = i + stride;
        const bool hasj = (j < n4);

        const float4 a0  = a4[i];
        const float4 o0  = __ldcs(o4 + i);
        const float4 cc0 = __ldcs(c4 + i);
        float4 a1, o1, cc1;
        if (hasj) {
            a1  = a4[j];
            o1  = __ldcs(o4 + j);
            cc1 = __ldcs(c4 + j);
        }

        const float* av0 = (const float*)&a0;
        const float* ov0 = (const float*)&o0;
        const float* cv0 = (const float*)&cc0;
        #pragma unroll
        for (int k = 0; k < 4; ++k) {
            const float ratio = __fdividef(cv0[k], ov0[k] + EPSF);
            const float adv   = (av0[k] - mean) * rstd;
            const float cl    = fminf(fmaxf(ratio, 1.f - CLIPP), 1.f + CLIPP);
            ppo += fminf(ratio * adv, cl * adv);
            ent  = fmaf(cv0[k], __logf(cv0[k] + EPSF), ent);
        }
        if (hasj) {
            const float* av1 = (const float*)&a1;
            const float* ov1 = (const float*)&o1;
            const float* cv1 = (const float*)&cc1;
            #pragma unroll
            for (int k = 0; k < 4; ++k) {
                const float ratio = __fdividef(cv1[k], ov1[k] + EPSF);
                const float adv   = (av1[k] - mean) * rstd;
                const float cl    = fminf(fmaxf(ratio, 1.f - CLIPP), 1.f + CLIPP);
                ppo += fminf(ratio * adv, cl * adv);
                ent  = fmaf(cv1[k], __logf(cv1[k] + EPSF), ent);
            }
        }
    }

    #pragma unroll
    for (int off = 16; off; off >>= 1) {
        ppo += __shfl_down_sync(0xffffffffu, ppo, off);
        ent += __shfl_down_sync(0xffffffffu, ent, off);
    }

    __shared__ double s_p[8], s_e[8];
    const int lane = threadIdx.x & 31, wid = threadIdx.x >> 5;
    if (lane == 0) { s_p[wid] = (double)ppo; s_e[wid] = (double)ent; }
    __syncthreads();
    if (threadIdx.x == 0) {
        double bp = 0.0, be = 0.0;
        #pragma unroll
        for (int i = 0; i < 8; ++i) { bp += s_p[i]; be += s_e[i]; }
        atomicAdd(&g_ppo, bp);
        atomicAdd(&g_ent, be);
    }
}

// ---------------------------------------------------------------- pass 3
__global__ void finalize_kernel(float* __restrict__ out) {
    const double n   = (double)NTOT;
    const double ppo = -(g_ppo / n);
    const double vls = 0.5  * (g_sumsq / n);   // value_loss = mean(adv^2)
    const double ent = -0.01 * (g_ent / n);
    out[0] = (float)(ppo + vls + ent);
    out[1] = (float)ppo;
    out[2] = (float)vls;
    out[3] = (float)ent;
    // reset for the next graph replay (deterministic start state)
    g_sum = 0.0; g_sumsq = 0.0; g_ppo = 0.0; g_ent = 0.0;
}

extern "C" void kernel_launch(void* const* d_in, const int* in_sizes, int n_in,
                              void* d_out, int out_size)
{
    // `values` has the unique size B*(T+1); everything else keeps metadata
    // order: rewards, ref_probs (unused), old_probs, curr_probs, masks.
    int vi = 1;
    for (int i = 0; i < n_in; ++i)
        if (in_sizes[i] == B * (T + 1)) { vi = i; break; }

    const float* others[8];
    int k = 0;
    for (int i = 0; i < n_in; ++i)
        if (i != vi) others[k++] = (const float*)d_in[i];

    const float* rewards = others[0];
    const float* old_p   = others[2];
    const float* curr_p  = others[3];
    const float* masks   = others[4];
    const float* values  = (const float*)d_in[vi];

    gae_kernel<<<B / 4, 128>>>(rewards, values, masks);   // 1024 CTAs, 1 warp/row
    loss_kernel<<<1184, 256>>>(old_p, curr_p);
    finalize_kernel<<<1, 1>>>((float*)d_out);
}

// round 7
// speedup vs baseline: 1.1341x; 1.1341x over previous
#include <cuda_runtime.h>
#include <cuda_fp16.h>

// PPO loss + GAE, B=4096 x T=2048 — single persistent fused kernel.
//
// Grid = 592 CTAs (4/SM x 148 SMs) x 128 threads, 7 rows per CTA.
// Residency: static smem 28KB (limit-derived 7 CTAs/SM), 128 threads,
// <=128 regs -> all 592 CTAs resident in wave 1, so the grid-wide spin
// sync is deadlock-free with large margin.
//
// Phase 1: per-warp blocked affine suffix scan (CHUNK=8, 256 steps per
//          warp-scan segment) of adv[t] = d[t] + c[t]*adv[t+1].
//          Advantages stored to SHARED MEMORY as fp16 (no HBM scratch).
//          Accumulates exact fp32->double sum(adv), sum(adv^2);
//          value_loss = mean((returns-values)^2) = mean(adv^2).
// Sync:    threadfence + atomic counter, spin until all CTAs arrive.
// Phase 2: mean/rstd from global sums; clipped PPO surrogate + entropy
//          over old/curr (streaming float4) with adv from smem.
// Finish:  last CTA to complete writes the 4 outputs and resets all
//          device globals (deterministic across graph replays).
//
// Traffic: 96MB (phase 1) + 64MB (phase 2) = 160MB, vs 224MB for the
// 3-kernel version with a gmem adv scratch.

namespace {
constexpr int B = 4096;
constexpr int T = 2048;
constexpr long long NTOT = (long long)B * T;   // 8388608
constexpr float GAMMA = 0.99f;
constexpr float LAM   = 0.95f;
constexpr float GL    = GAMMA * LAM;
constexpr float CLIPP = 0.2f;
constexpr float EPSF  = 1e-9f;

constexpr int CHUNK = 8;                 // timesteps per lane per segment
constexpr int SEG   = 32 * CHUNK;        // 256 timesteps per warp scan
constexpr int NSEG  = T / SEG;           // 8

constexpr int GRID  = 592;               // 4 CTAs/SM x 148 SMs
constexpr int RPC   = 7;                 // rows per CTA (592*7 = 4144 >= 4096)
}

__device__ double g_sum, g_sumsq, g_ppo, g_ent;   // zero-init; reset each replay
__device__ int    g_c1, g_c2;                      // phase counters

__global__ __launch_bounds__(128, 4) void ppo_fused_kernel(
    const float* __restrict__ rewards,
    const float* __restrict__ values,
    const float* __restrict__ masks,
    const float* __restrict__ old_p,
    const float* __restrict__ curr_p,
    float* __restrict__ out)
{
    __shared__ __half s_adv[RPC][T];     // 28 KB fp16 advantages
    __shared__ double s_a[4], s_b[4];
    __shared__ float  sh_mean, sh_rstd;

    const int tid  = threadIdx.x;
    const int lane = tid & 31;
    const int wid  = tid >> 5;
    const unsigned FULL = 0xffffffffu;

    // ================= Phase 1: GAE -> smem fp16, moment sums =================
    float lsum = 0.f, lsq = 0.f;

    for (int i = wid; i < RPC; i += 4) {
        const int row = blockIdx.x + GRID * i;
        if (row >= B) continue;

        const float* rr = rewards + (size_t)row * T;
        const float* vr = values  + (size_t)row * (T + 1);
        const float* mr = masks   + (size_t)row * T;
        __half*      ar = &s_adv[i][0];

        float carry = 0.f;   // adv just past the current segment (adv[T]=0)

        for (int seg = NSEG - 1; seg >= 0; --seg) {
            const int base = seg * SEG + lane * CHUNK;

            const float4 ra = __ldcs((const float4*)(rr + base));
            const float4 rb = __ldcs((const float4*)(rr + base + 4));
            const float4 ma = __ldcs((const float4*)(mr + base));
            const float4 mb = __ldcs((const float4*)(mr + base + 4));
            float v[CHUNK + 1];
            #pragma unroll
            for (int j = 0; j <= CHUNK; ++j) v[j] = __ldcs(vr + base + j);

            const float r_[CHUNK] = {ra.x, ra.y, ra.z, ra.w, rb.x, rb.y, rb.z, rb.w};
            const float m_[CHUNK] = {ma.x, ma.y, ma.z, ma.w, mb.x, mb.y, mb.z, mb.w};

            float c[CHUNK], d[CHUNK];
            #pragma unroll
            for (int j = 0; j < CHUNK; ++j) {
                c[j] = GL * m_[j];
                d[j] = fmaf(GAMMA * v[j + 1], m_[j], r_[j]) - v[j];
            }

            // local suffix composition over this lane's 8 steps
            float C = c[CHUNK - 1], D = d[CHUNK - 1];
            #pragma unroll
            for (int j = CHUNK - 2; j >= 0; --j) {
                D = fmaf(c[j], D, d[j]);
                C = c[j] * C;
            }

            // warp inclusive suffix scan of the 32 per-lane maps
            #pragma unroll
            for (int off = 1; off < 32; off <<= 1) {
                const float C2 = __shfl_down_sync(FULL, C, off);
                const float D2 = __shfl_down_sync(FULL, D, off);
                if (lane + off < 32) {
                    D = fmaf(C, D2, D);
                    C = C * C2;
                }
            }

            // x = adv at my chunk's end+1 (maps of lanes > me applied to carry)
            const float Cx = __shfl_down_sync(FULL, C, 1);
            const float Dx = __shfl_down_sync(FULL, D, 1);
            float x = (lane == 31) ? carry : fmaf(Cx, carry, Dx);

            float a[CHUNK];
            #pragma unroll
            for (int j = CHUNK - 1; j >= 0; --j) {
                a[j] = fmaf(c[j], x, d[j]);
                x = a[j];
            }
            carry = __shfl_sync(FULL, x, 0);

            // pack 8 fp16 and store 16B to smem
            const __half2 h0 = __floats2half2_rn(a[0], a[1]);
            const __half2 h1 = __floats2half2_rn(a[2], a[3]);
            const __half2 h2 = __floats2half2_rn(a[4], a[5]);
            const __half2 h3 = __floats2half2_rn(a[6], a[7]);
            uint4 pk;
            pk.x = *(const unsigned*)&h0;  pk.y = *(const unsigned*)&h1;
            pk.z = *(const unsigned*)&h2;  pk.w = *(const unsigned*)&h3;
            *(uint4*)(ar + base) = pk;

            #pragma unroll
            for (int j = 0; j < CHUNK; ++j) {
                lsum += a[j];
                lsq = fmaf(a[j], a[j], lsq);
            }
        }
    }

    // CTA reduce of the moments
    #pragma unroll
    for (int off = 16; off; off >>= 1) {
        lsum += __shfl_down_sync(FULL, lsum, off);
        lsq  += __shfl_down_sync(FULL, lsq,  off);
    }
    if (lane == 0) { s_a[wid] = (double)lsum; s_b[wid] = (double)lsq; }
    __syncthreads();
    if (tid == 0) {
        double bs = 0.0, bq = 0.0;
        #pragma unroll
        for (int i = 0; i < 4; ++i) { bs += s_a[i]; bq += s_b[i]; }
        atomicAdd(&g_sum,   bs);
        atomicAdd(&g_sumsq, bq);
        __threadfence();
        atomicAdd(&g_c1, 1);
        // spin until every CTA's moments are in (all CTAs resident: safe)
        while (atomicAdd(&g_c1, 0) < GRID) __nanosleep(64);
        const double n    = (double)NTOT;
        const double mean = g_sum / n;
        const double var  = (g_sumsq - g_sum * g_sum / n) / (n - 1.0);  // ddof=1
        sh_mean = (float)mean;
        sh_rstd = (float)(1.0 / (sqrt(var) + (double)EPSF));
    }
    __syncthreads();

    // ================= Phase 2: PPO surrogate + entropy =================
    const float mean = sh_mean, rstd = sh_rstd;
    float ppo = 0.f, ent = 0.f;

    for (int i = 0; i < RPC; ++i) {
        const int row = blockIdx.x + GRID * i;
        if (row >= B) continue;

        const float4* o4 = (const float4*)(old_p  + (size_t)row * T);
        const float4* c4 = (const float4*)(curr_p + (size_t)row * T);
        const __half* ar = &s_adv[i][0];

        #pragma unroll
        for (int cch = 0; cch < 4; ++cch) {
            const int idx = cch * 128 + tid;     // float4 index within row (512 total)
            const float4 o  = __ldcs(o4 + idx);
            const float4 cc = __ldcs(c4 + idx);
            const uint2 hh = *(const uint2*)(ar + idx * 4);
            const __half2 ha = *(const __half2*)&hh.x;
            const __half2 hb = *(const __half2*)&hh.y;
            const float2 fa = __half22float2(ha);
            const float2 fb = __half22float2(hb);

            const float av[4] = {fa.x, fa.y, fb.x, fb.y};
            const float* ov = (const float*)&o;
            const float* cv = (const float*)&cc;
            #pragma unroll
            for (int k = 0; k < 4; ++k) {
                const float ratio = __fdividef(cv[k], ov[k] + EPSF);
                const float adv   = (av[k] - mean) * rstd;
                const float cl    = fminf(fmaxf(ratio, 1.f - CLIPP), 1.f + CLIPP);
                ppo += fminf(ratio * adv, cl * adv);
                ent  = fmaf(cv[k], __logf(cv[k] + EPSF), ent);
            }
        }
    }

    #pragma unroll
    for (int off = 16; off; off >>= 1) {
        ppo += __shfl_down_sync(FULL, ppo, off);
        ent += __shfl_down_sync(FULL, ent, off);
    }
    __syncthreads();   // s_a/s_b reuse
    if (lane == 0) { s_a[wid] = (double)ppo; s_b[wid] = (double)ent; }
    __syncthreads();

    if (tid == 0) {
        double bp = 0.0, be = 0.0;
        #pragma unroll
        for (int i = 0; i < 4; ++i) { bp += s_a[i]; be += s_b[i]; }
        atomicAdd(&g_ppo, bp);
        atomicAdd(&g_ent, be);
        __threadfence();
        const int done = atomicAdd(&g_c2, 1);
        if (done == GRID - 1) {
            // last CTA: finalize output, reset state for the next replay
            const double n   = (double)NTOT;
            const double pl  = -(g_ppo / n);
            const double vls = 0.5  * (g_sumsq / n);   // value_loss = mean(adv^2)
            const double el  = -0.01 * (g_ent / n);
            out[0] = (float)(pl + vls + el);
            out[1] = (float)pl;
            out[2] = (float)vls;
            out[3] = (float)el;
            g_sum = 0.0; g_sumsq = 0.0; g_ppo = 0.0; g_ent = 0.0;
            g_c1 = 0; g_c2 = 0;
            __threadfence();
        }
    }
}

extern "C" void kernel_launch(void* const* d_in, const int* in_sizes, int n_in,
                              void* d_out, int out_size)
{
    // `values` has the unique size B*(T+1); everything else keeps metadata
    // order: rewards, ref_probs (unused), old_probs, curr_probs, masks.
    int vi = 1;
    for (int i = 0; i < n_in; ++i)
        if (in_sizes[i] == B * (T + 1)) { vi = i; break; }

    const float* others[8];
    int k = 0;
    for (int i = 0; i < n_in; ++i)
        if (i != vi) others[k++] = (const float*)d_in[i];

    const float* rewards = others[0];
    const float* old_p   = others[2];
    const float* curr_p  = others[3];
    const float* masks   = others[4];
    const float* values  = (const float*)d_in[vi];

    ppo_fused_kernel<<<GRID, 128>>>(rewards, values, masks, old_p, curr_p,
                                    (float*)d_out);
}

// round 8
// speedup vs baseline: 1.3366x; 1.1786x over previous
#include <cuda_runtime.h>
#include <cuda_fp16.h>

// PPO loss + GAE, B=4096 x T=2048 — single persistent fused kernel.
//
// Grid = 1024 CTAs x 128 threads, 4 rows per CTA (exactly 4096 rows).
// Residency: smem 16KB -> cap 14 CTAs/SM; threads -> 16; regs (<=73 via
// __launch_bounds__(128,7)) -> >=7. Wave 1 needs max ceil(1024/148)=7
// CTAs/SM, so ALL CTAs are resident and the grid-wide spin sync is safe.
//
// Phase 1: one warp per row. Blocked affine suffix scan (CHUNK=8, 256
//          steps per warp-scan segment) of adv[t]=d[t]+c[t]*adv[t+1].
//          Advantages staged in SHARED MEMORY as fp16 (no HBM scratch).
//          Exact fp32->double sum(adv), sum(adv^2);
//          value_loss = mean((returns-values)^2) = mean(adv^2).
// Sync:    threadfence + atomic counter, spin until all CTAs arrive.
// Phase 2: mean/rstd from global sums; clipped PPO surrogate + entropy
//          over old/curr (streaming float4) with adv from smem.
// Finish:  last CTA writes the 4 outputs and resets all device globals
//          (deterministic across graph replays).
//
// Traffic: 96MB (phase 1) + 64MB (phase 2) = 160MB.

namespace {
constexpr int B = 4096;
constexpr int T = 2048;
constexpr long long NTOT = (long long)B * T;   // 8388608
constexpr float GAMMA = 0.99f;
constexpr float LAM   = 0.95f;
constexpr float GL    = GAMMA * LAM;
constexpr float CLIPP = 0.2f;
constexpr float EPSF  = 1e-9f;

constexpr int CHUNK = 8;                 // timesteps per lane per segment
constexpr int SEG   = 32 * CHUNK;        // 256 timesteps per warp scan
constexpr int NSEG  = T / SEG;           // 8

constexpr int GRID  = 1024;              // CTAs (all resident: 7/SM max)
constexpr int RPC   = 4;                 // rows per CTA (1024*4 = 4096)
}

__device__ double g_sum, g_sumsq, g_ppo, g_ent;   // zero-init; reset each replay
__device__ int    g_c1, g_c2;                      // phase counters

__global__ __launch_bounds__(128, 7) void ppo_fused_kernel(
    const float* __restrict__ rewards,
    const float* __restrict__ values,
    const float* __restrict__ masks,
    const float* __restrict__ old_p,
    const float* __restrict__ curr_p,
    float* __restrict__ out)
{
    __shared__ __half s_adv[RPC][T];     // 16 KB fp16 advantages
    __shared__ double s_a[4], s_b[4];
    __shared__ float  sh_mean, sh_rstd;

    const int tid  = threadIdx.x;
    const int lane = tid & 31;
    const int wid  = tid >> 5;
    const unsigned FULL = 0xffffffffu;

    // ================= Phase 1: GAE -> smem fp16, moment sums =================
    float lsum = 0.f, lsq = 0.f;

    {
        const int row = blockIdx.x + GRID * wid;     // one warp per row

        const float* rr = rewards + (size_t)row * T;
        const float* vr = values  + (size_t)row * (T + 1);
        const float* mr = masks   + (size_t)row * T;
        __half*      ar = &s_adv[wid][0];

        float carry = 0.f;   // adv just past the current segment (adv[T]=0)

        for (int seg = NSEG - 1; seg >= 0; --seg) {
            const int base = seg * SEG + lane * CHUNK;

            const float4 ra = __ldcs((const float4*)(rr + base));
            const float4 rb = __ldcs((const float4*)(rr + base + 4));
            const float4 ma = __ldcs((const float4*)(mr + base));
            const float4 mb = __ldcs((const float4*)(mr + base + 4));
            float v[CHUNK + 1];
            #pragma unroll
            for (int j = 0; j <= CHUNK; ++j) v[j] = __ldcs(vr + base + j);

            const float r_[CHUNK] = {ra.x, ra.y, ra.z, ra.w, rb.x, rb.y, rb.z, rb.w};
            const float m_[CHUNK] = {ma.x, ma.y, ma.z, ma.w, mb.x, mb.y, mb.z, mb.w};

            float c[CHUNK], d[CHUNK];
            #pragma unroll
            for (int j = 0; j < CHUNK; ++j) {
                c[j] = GL * m_[j];
                d[j] = fmaf(GAMMA * v[j + 1], m_[j], r_[j]) - v[j];
            }

            // local suffix composition over this lane's 8 steps
            float C = c[CHUNK - 1], D = d[CHUNK - 1];
            #pragma unroll
            for (int j = CHUNK - 2; j >= 0; --j) {
                D = fmaf(c[j], D, d[j]);
                C = c[j] * C;
            }

            // warp inclusive suffix scan of the 32 per-lane maps
            #pragma unroll
            for (int off = 1; off < 32; off <<= 1) {
                const float C2 = __shfl_down_sync(FULL, C, off);
                const float D2 = __shfl_down_sync(FULL, D, off);
                if (lane + off < 32) {
                    D = fmaf(C, D2, D);
                    C = C * C2;
                }
            }

            // x = adv at my chunk's end+1 (maps of lanes > me applied to carry)
            const float Cx = __shfl_down_sync(FULL, C, 1);
            const float Dx = __shfl_down_sync(FULL, D, 1);
            float x = (lane == 31) ? carry : fmaf(Cx, carry, Dx);

            float a[CHUNK];
            #pragma unroll
            for (int j = CHUNK - 1; j >= 0; --j) {
                a[j] = fmaf(c[j], x, d[j]);
                x = a[j];
            }
            carry = __shfl_sync(FULL, x, 0);

            // pack 8 fp16 and store 16B to smem
            const __half2 h0 = __floats2half2_rn(a[0], a[1]);
            const __half2 h1 = __floats2half2_rn(a[2], a[3]);
            const __half2 h2 = __floats2half2_rn(a[4], a[5]);
            const __half2 h3 = __floats2half2_rn(a[6], a[7]);
            uint4 pk;
            pk.x = *(const unsigned*)&h0;  pk.y = *(const unsigned*)&h1;
            pk.z = *(const unsigned*)&h2;  pk.w = *(const unsigned*)&h3;
            *(uint4*)(ar + base) = pk;

            #pragma unroll
            for (int j = 0; j < CHUNK; ++j) {
                lsum += a[j];
                lsq = fmaf(a[j], a[j], lsq);
            }
        }
    }

    // CTA reduce of the moments
    #pragma unroll
    for (int off = 16; off; off >>= 1) {
        lsum += __shfl_down_sync(FULL, lsum, off);
        lsq  += __shfl_down_sync(FULL, lsq,  off);
    }
    if (lane == 0) { s_a[wid] = (double)lsum; s_b[wid] = (double)lsq; }
    __syncthreads();
    if (tid == 0) {
        double bs = 0.0, bq = 0.0;
        #pragma unroll
        for (int i = 0; i < 4; ++i) { bs += s_a[i]; bq += s_b[i]; }
        atomicAdd(&g_sum,   bs);
        atomicAdd(&g_sumsq, bq);
        __threadfence();
        atomicAdd(&g_c1, 1);
        // spin until every CTA's moments are in (all CTAs resident: safe)
        while (atomicAdd(&g_c1, 0) < GRID) __nanosleep(64);
        const double n    = (double)NTOT;
        const double mean = g_sum / n;
        const double var  = (g_sumsq - g_sum * g_sum / n) / (n - 1.0);  // ddof=1
        sh_mean = (float)mean;
        sh_rstd = (float)(1.0 / (sqrt(var) + (double)EPSF));
    }
    __syncthreads();

    // ================= Phase 2: PPO surrogate + entropy =================
    const float mean = sh_mean, rstd = sh_rstd;
    float ppo = 0.f, ent = 0.f;

    #pragma unroll
    for (int i = 0; i < RPC; ++i) {
        const int row = blockIdx.x + GRID * i;

        const float4* o4 = (const float4*)(old_p  + (size_t)row * T);
        const float4* c4 = (const float4*)(curr_p + (size_t)row * T);
        const __half* ar = &s_adv[i][0];

        #pragma unroll
        for (int cch = 0; cch < 4; ++cch) {
            const int idx = cch * 128 + tid;     // float4 index within row (512 total)
            const float4 o  = __ldcs(o4 + idx);
            const float4 cc = __ldcs(c4 + idx);
            const uint2 hh = *(const uint2*)(ar + idx * 4);
            const __half2 ha = *(const __half2*)&hh.x;
            const __half2 hb = *(const __half2*)&hh.y;
            const float2 fa = __half22float2(ha);
            const float2 fb = __half22float2(hb);

            const float av[4] = {fa.x, fa.y, fb.x, fb.y};
            const float* ov = (const float*)&o;
            const float* cv = (const float*)&cc;
            #pragma unroll
            for (int k = 0; k < 4; ++k) {
                const float ratio = __fdividef(cv[k], ov[k] + EPSF);
                const float adv   = (av[k] - mean) * rstd;
                const float cl    = fminf(fmaxf(ratio, 1.f - CLIPP), 1.f + CLIPP);
                ppo += fminf(ratio * adv, cl * adv);
                ent  = fmaf(cv[k], __logf(cv[k] + EPSF), ent);
            }
        }
    }

    #pragma unroll
    for (int off = 16; off; off >>= 1) {
        ppo += __shfl_down_sync(FULL, ppo, off);
        ent += __shfl_down_sync(FULL, ent, off);
    }
    __syncthreads();   // s_a/s_b reuse
    if (lane == 0) { s_a[wid] = (double)ppo; s_b[wid] = (double)ent; }
    __syncthreads();

    if (tid == 0) {
        double bp = 0.0, be = 0.0;
        #pragma unroll
        for (int i = 0; i < 4; ++i) { bp += s_a[i]; be += s_b[i]; }
        atomicAdd(&g_ppo, bp);
        atomicAdd(&g_ent, be);
        __threadfence();
        const int done = atomicAdd(&g_c2, 1);
        if (done == GRID - 1) {
            // last CTA: finalize output, reset state for the next replay
            const double n   = (double)NTOT;
            const double pl  = -(g_ppo / n);
            const double vls = 0.5  * (g_sumsq / n);   // value_loss = mean(adv^2)
            const double el  = -0.01 * (g_ent / n);
            out[0] = (float)(pl + vls + el);
            out[1] = (float)pl;
            out[2] = (float)vls;
            out[3] = (float)el;
            g_sum = 0.0; g_sumsq = 0.0; g_ppo = 0.0; g_ent = 0.0;
            g_c1 = 0; g_c2 = 0;
            __threadfence();
        }
    }
}

extern "C" void kernel_launch(void* const* d_in, const int* in_sizes, int n_in,
                              void* d_out, int out_size)
{
    // `values` has the unique size B*(T+1); everything else keeps metadata
    // order: rewards, ref_probs (unused), old_probs, curr_probs, masks.
    int vi = 1;
    for (int i = 0; i < n_in; ++i)
        if (in_sizes[i] == B * (T + 1)) { vi = i; break; }

    const float* others[8];
    int k = 0;
    for (int i = 0; i < n_in; ++i)
        if (i != vi) others[k++] = (const float*)d_in[i];

    const float* rewards = others[0];
    const float* old_p   = others[2];
    const float* curr_p  = others[3];
    const float* masks   = others[4];
    const float* values  = (const float*)d_in[vi];

    ppo_fused_kernel<<<GRID, 128>>>(rewards, values, masks, old_p, curr_p,
                                    (float*)d_out);
}